// round 1
// baseline (speedup 1.0000x reference)
#include <cuda_runtime.h>
#include <cuda_bf16.h>

#define NNODES 20000
#define NPAD   20032
#define MCOLS  1024
#define NEDGE  640000
#define DD     256

// ---------------- scratch (__device__ globals; zero-initialized bss) ----------------
__device__ float g_colemb[MCOLS * DD];
__device__ float g_x0[NPAD * DD];
__device__ float g_h[NPAD * DD];
__device__ float g_bufA[NPAD * DD];
__device__ float g_bufB[NPAD * DD];
__device__ float g_br0[NPAD * DD];
__device__ float g_br1[NPAD * DD];
__device__ float g_br2[NPAD * DD];
__device__ float g_deg[NNODES];
__device__ float g_dinv[NNODES];
__device__ int   g_hist[NNODES];
__device__ int   g_cur[NNODES];
__device__ int   g_start[NNODES + 1];
__device__ int   g_src[NEDGE];
__device__ float g_nrm[NEDGE];

// ---------------- projection: col_emb[j][d] = relu(j*pW1+pb1) @ pW2 + pb2 ----------------
__global__ void colemb_kernel(const float* __restrict__ pW1, const float* __restrict__ pb1,
                              const float* __restrict__ pW2, const float* __restrict__ pb2,
                              float* __restrict__ colemb) {
    int j = blockIdx.x;
    int d = threadIdx.x;
    float jf = (float)j;
    float acc = pb2[d];
#pragma unroll
    for (int k = 0; k < 16; k++) {
        float hk = fmaxf(jf * pW1[k] + pb1[k], 0.f);
        acc += hk * pW2[k * DD + d];
    }
    colemb[j * DD + d] = acc;
}

// ---------------- x0: masked mean of col_emb rows over nonzero cols of init ----------------
__global__ void x0_kernel(const float* __restrict__ init, const float* __restrict__ colemb,
                          float* __restrict__ x0) {
    int i = blockIdx.x;
    int t = threadIdx.x;  // 256
    __shared__ unsigned short nz[MCOLS];
    __shared__ int cnt;
    if (t == 0) cnt = 0;
    __syncthreads();
    const float* row = init + (size_t)i * MCOLS;
    for (int c = t; c < MCOLS; c += 256) {
        if (row[c] != 0.f) {
            int p = atomicAdd(&cnt, 1);
            nz[p] = (unsigned short)c;
        }
    }
    __syncthreads();
    int n = cnt;
    float acc = 0.f;
    for (int k = 0; k < n; k++) {
        acc += colemb[(int)nz[k] * DD + t];
    }
    x0[i * DD + t] = (n > 0) ? acc / (float)n : 0.f;
}

// ---------------- per-branch graph prep ----------------
__global__ void branch_init(float* __restrict__ deg, int* __restrict__ hist) {
    int i = blockIdx.x * blockDim.x + threadIdx.x;
    if (i < NNODES) { deg[i] = 1.0f; hist[i] = 0; }  // self-loop weight 1
}

__global__ void edge_count(const int* __restrict__ ei, const float* __restrict__ ea,
                           float* __restrict__ deg, int* __restrict__ hist) {
    int e = blockIdx.x * blockDim.x + threadIdx.x;
    if (e < NEDGE) {
        int c = ei[NEDGE + e];  // col = destination
        atomicAdd(&deg[c], ea[e]);
        atomicAdd(&hist[c], 1);
    }
}

__global__ void dinv_kernel(const float* __restrict__ deg, float* __restrict__ dinv) {
    int i = blockIdx.x * blockDim.x + threadIdx.x;
    if (i < NNODES) dinv[i] = rsqrtf(deg[i]);
}

// single-block exclusive scan of hist -> start, cur
__global__ void scan_kernel(const int* __restrict__ hist, int* __restrict__ start,
                            int* __restrict__ cur) {
    __shared__ int sm[1024];
    __shared__ int carry_s;
    int t = threadIdx.x;
    if (t == 0) carry_s = 0;
    __syncthreads();
    for (int c0 = 0; c0 < NNODES; c0 += 1024) {
        int idx = c0 + t;
        int v = (idx < NNODES) ? hist[idx] : 0;
        sm[t] = v;
        __syncthreads();
        for (int off = 1; off < 1024; off <<= 1) {
            int x = (t >= off) ? sm[t - off] : 0;
            __syncthreads();
            sm[t] += x;
            __syncthreads();
        }
        int incl = sm[t];
        int base = carry_s;
        __syncthreads();
        if (t == 1023) carry_s = base + incl;
        int excl = base + incl - v;
        if (idx < NNODES) { start[idx] = excl; cur[idx] = excl; }
        __syncthreads();
    }
    if (t == 0) start[NNODES] = carry_s;
}

__global__ void scatter_kernel(const int* __restrict__ ei, const float* __restrict__ ea,
                               const float* __restrict__ dinv, int* __restrict__ cur,
                               int* __restrict__ src, float* __restrict__ nrm) {
    int e = blockIdx.x * blockDim.x + threadIdx.x;
    if (e < NEDGE) {
        int r = ei[e];
        int c = ei[NEDGE + e];
        float n = dinv[r] * ea[e] * dinv[c];
        int p = atomicAdd(&cur[c], 1);
        src[p] = r;
        nrm[p] = n;
    }
}

// ---------------- GEMM: C[NPAD,256] = act(A) @ W, W row-major [256,256] ----------------
#define BM 64
#define BN 64
#define BK 32
__global__ void gemm_kernel(const float* __restrict__ A, const float* __restrict__ W,
                            float* __restrict__ C, int relu_in) {
    __shared__ float As[BK][BM + 4];
    __shared__ float Bs[BK][BN];
    int bm = blockIdx.x * BM;
    int bn = blockIdx.y * BN;
    int tid = threadIdx.x;          // 256
    int tx = tid & 15;              // n-tile
    int ty = tid >> 4;              // m-tile
    float acc[4][4];
#pragma unroll
    for (int i = 0; i < 4; i++)
#pragma unroll
        for (int j = 0; j < 4; j++) acc[i][j] = 0.f;

    for (int k0 = 0; k0 < DD; k0 += BK) {
        // A tile: 64x32 = 512 float4, 2 per thread; transpose into As[k][m]
#pragma unroll
        for (int i = 0; i < 2; i++) {
            int f = tid + i * 256;
            int row = f >> 3;
            int cv = f & 7;
            float4 v = *(const float4*)&A[(size_t)(bm + row) * DD + k0 + cv * 4];
            if (relu_in) {
                v.x = fmaxf(v.x, 0.f); v.y = fmaxf(v.y, 0.f);
                v.z = fmaxf(v.z, 0.f); v.w = fmaxf(v.w, 0.f);
            }
            As[cv * 4 + 0][row] = v.x;
            As[cv * 4 + 1][row] = v.y;
            As[cv * 4 + 2][row] = v.z;
            As[cv * 4 + 3][row] = v.w;
        }
        // B tile: 32x64 = 512 float4, 2 per thread
#pragma unroll
        for (int i = 0; i < 2; i++) {
            int f = tid + i * 256;
            int row = f >> 4;
            int cv = f & 15;
            float4 v = *(const float4*)&W[(size_t)(k0 + row) * DD + bn + cv * 4];
            *(float4*)&Bs[row][cv * 4] = v;
        }
        __syncthreads();
#pragma unroll
        for (int kk = 0; kk < BK; kk++) {
            float a[4], b[4];
            *(float4*)a = *(const float4*)&As[kk][ty * 4];
            *(float4*)b = *(const float4*)&Bs[kk][tx * 4];
#pragma unroll
            for (int i = 0; i < 4; i++)
#pragma unroll
                for (int j = 0; j < 4; j++) acc[i][j] += a[i] * b[j];
        }
        __syncthreads();
    }
#pragma unroll
    for (int i = 0; i < 4; i++) {
        float4 v = make_float4(acc[i][0], acc[i][1], acc[i][2], acc[i][3]);
        *(float4*)&C[(size_t)(bm + ty * 4 + i) * DD + bn + tx * 4] = v;
    }
}

// ---------------- aggregation: out[i] = sum_k nrm[k]*h[src[k]] + dinv[i]^2*h[i] + b ----------------
__global__ void agg_kernel(const float* __restrict__ h, const int* __restrict__ src,
                           const float* __restrict__ nrm, const int* __restrict__ start,
                           const float* __restrict__ dinv, const float* __restrict__ bias,
                           float* __restrict__ out) {
    int i = blockIdx.x;
    int t = threadIdx.x;  // 64, float4 each
    int s = start[i];
    int e = start[i + 1];
    float4 acc = make_float4(0.f, 0.f, 0.f, 0.f);
    for (int k = s; k < e; k++) {
        int r = src[k];
        float w = nrm[k];
        float4 v = *(const float4*)&h[(size_t)r * DD + t * 4];
        acc.x += w * v.x; acc.y += w * v.y; acc.z += w * v.z; acc.w += w * v.w;
    }
    float di = dinv[i];
    float sn = di * di;
    float4 hv = *(const float4*)&h[(size_t)i * DD + t * 4];
    float4 bv = *(const float4*)&bias[t * 4];
    acc.x += sn * hv.x + bv.x;
    acc.y += sn * hv.y + bv.y;
    acc.z += sn * hv.z + bv.z;
    acc.w += sn * hv.w + bv.w;
    *(float4*)&out[(size_t)i * DD + t * 4] = acc;
}

// ---------------- meta-path attention ----------------
__global__ void attn_kernel(const float* __restrict__ b0, const float* __restrict__ b1,
                            const float* __restrict__ b2, const float* __restrict__ watt,
                            float* __restrict__ out) {
    int i = blockIdx.x;
    int t = threadIdx.x;  // 256
    size_t off = (size_t)i * DD + t;
    float x0v = fmaxf(b0[off], 0.f);
    float x1v = fmaxf(b1[off], 0.f);
    float x2v = fmaxf(b2[off], 0.f);
    float w = watt[t];
    float s0 = x0v * w, s1 = x1v * w, s2 = x2v * w;
#pragma unroll
    for (int o = 16; o; o >>= 1) {
        s0 += __shfl_xor_sync(0xffffffffu, s0, o);
        s1 += __shfl_xor_sync(0xffffffffu, s1, o);
        s2 += __shfl_xor_sync(0xffffffffu, s2, o);
    }
    __shared__ float sm[3][8];
    __shared__ float sw[3];
    int wid = t >> 5, ln = t & 31;
    if (ln == 0) { sm[0][wid] = s0; sm[1][wid] = s1; sm[2][wid] = s2; }
    __syncthreads();
    if (t == 0) {
        float t0 = 0.f, t1 = 0.f, t2 = 0.f;
#pragma unroll
        for (int k = 0; k < 8; k++) { t0 += sm[0][k]; t1 += sm[1][k]; t2 += sm[2][k]; }
        float mx = fmaxf(t0, fmaxf(t1, t2));
        float e0 = expf(t0 - mx), e1 = expf(t1 - mx), e2 = expf(t2 - mx);
        float inv = 1.f / (e0 + e1 + e2);
        sw[0] = e0 * inv; sw[1] = e1 * inv; sw[2] = e2 * inv;
    }
    __syncthreads();
    out[off] = sw[0] * x0v + sw[1] * x1v + sw[2] * x2v;
}

// ---------------- launcher ----------------
extern "C" void kernel_launch(void* const* d_in, const int* in_sizes, int n_in,
                              void* d_out, int out_size) {
    const float* init = (const float*)d_in[0];
    const int*   ei[3] = {(const int*)d_in[1], (const int*)d_in[2], (const int*)d_in[3]};
    const float* ea[3] = {(const float*)d_in[4], (const float*)d_in[5], (const float*)d_in[6]};
    const float* pW1 = (const float*)d_in[7];
    const float* pb1 = (const float*)d_in[8];
    const float* pW2 = (const float*)d_in[9];
    const float* pb2 = (const float*)d_in[10];
    const float* Wb[3] = {(const float*)d_in[11], (const float*)d_in[13], (const float*)d_in[15]};
    const float* bb[3] = {(const float*)d_in[12], (const float*)d_in[14], (const float*)d_in[16]};
    const float* watt = (const float*)d_in[17];
    float* out = (float*)d_out;

    float *colemb, *x0, *h, *bufA, *bufB, *deg, *dinv, *nrm;
    float *br[3];
    int *hist, *cur, *start, *src;
    cudaGetSymbolAddress((void**)&colemb, g_colemb);
    cudaGetSymbolAddress((void**)&x0,     g_x0);
    cudaGetSymbolAddress((void**)&h,      g_h);
    cudaGetSymbolAddress((void**)&bufA,   g_bufA);
    cudaGetSymbolAddress((void**)&bufB,   g_bufB);
    cudaGetSymbolAddress((void**)&br[0],  g_br0);
    cudaGetSymbolAddress((void**)&br[1],  g_br1);
    cudaGetSymbolAddress((void**)&br[2],  g_br2);
    cudaGetSymbolAddress((void**)&deg,    g_deg);
    cudaGetSymbolAddress((void**)&dinv,   g_dinv);
    cudaGetSymbolAddress((void**)&hist,   g_hist);
    cudaGetSymbolAddress((void**)&cur,    g_cur);
    cudaGetSymbolAddress((void**)&start,  g_start);
    cudaGetSymbolAddress((void**)&src,    g_src);
    cudaGetSymbolAddress((void**)&nrm,    g_nrm);

    colemb_kernel<<<MCOLS, DD>>>(pW1, pb1, pW2, pb2, colemb);
    x0_kernel<<<NNODES, 256>>>(init, colemb, x0);

    const int NB = (NNODES + 255) / 256;
    const int EB = (NEDGE + 255) / 256;

    for (int b = 0; b < 3; b++) {
        branch_init<<<NB, 256>>>(deg, hist);
        edge_count<<<EB, 256>>>(ei[b], ea[b], deg, hist);
        dinv_kernel<<<NB, 256>>>(deg, dinv);
        scan_kernel<<<1, 1024>>>(hist, start, cur);
        scatter_kernel<<<EB, 256>>>(ei[b], ea[b], dinv, cur, src, nrm);

        const float* x = x0;
        float* outs[3] = {bufA, bufB, br[b]};
        for (int l = 0; l < 3; l++) {
            gemm_kernel<<<dim3(NPAD / BM, DD / BN), 256>>>(x, Wb[b] + l * DD * DD, h, l > 0);
            agg_kernel<<<NNODES, 64>>>(h, src, nrm, start, dinv, bb[b] + l * DD, outs[l]);
            x = outs[l];
        }
    }

    attn_kernel<<<NNODES, 256>>>(br[0], br[1], br[2], watt, out);
}

// round 3
// speedup vs baseline: 1.1867x; 1.1867x over previous
#include <cuda_runtime.h>
#include <cuda_bf16.h>
#include <cstdint>

#define NNODES 20000
#define NPAD   20096            // 157 * 128
#define MCOLS  1024
#define NEDGE  640000
#define DD     256

// ---------------- scratch (__device__ globals; zero-initialized bss) ----------------
__device__ float g_colemb[MCOLS * DD];
__device__ float g_x0[NPAD * DD];
__device__ float g_h[NPAD * DD];
__device__ float g_bufA[NPAD * DD];
__device__ float g_bufB[NPAD * DD];
__device__ float g_br0[NPAD * DD];
__device__ float g_br1[NPAD * DD];
__device__ float g_br2[NPAD * DD];
__device__ float g_deg[NNODES];
__device__ float g_dinv[NNODES];
__device__ int   g_hist[NNODES];
__device__ int   g_cur[NNODES];
__device__ int   g_start[NNODES + 1];
__device__ int   g_src[NEDGE];
__device__ float g_nrm[NEDGE];

// ---------------- projection: col_emb ----------------
__global__ void colemb_kernel(const float* __restrict__ pW1, const float* __restrict__ pb1,
                              const float* __restrict__ pW2, const float* __restrict__ pb2,
                              float* __restrict__ colemb) {
    int j = blockIdx.x;
    int d = threadIdx.x;
    float jf = (float)j;
    float acc = pb2[d];
#pragma unroll
    for (int k = 0; k < 16; k++) {
        float hk = fmaxf(jf * pW1[k] + pb1[k], 0.f);
        acc += hk * pW2[k * DD + d];
    }
    colemb[j * DD + d] = acc;
}

// ---------------- x0: masked mean over nonzero cols ----------------
__global__ void x0_kernel(const float* __restrict__ init, const float* __restrict__ colemb,
                          float* __restrict__ x0) {
    int i = blockIdx.x;
    int t = threadIdx.x;  // 256
    __shared__ unsigned short nz[MCOLS];
    __shared__ int cnt;
    if (t == 0) cnt = 0;
    __syncthreads();
    const float* row = init + (size_t)i * MCOLS;
    for (int c = t; c < MCOLS; c += 256) {
        if (row[c] != 0.f) {
            int p = atomicAdd(&cnt, 1);
            nz[p] = (unsigned short)c;
        }
    }
    __syncthreads();
    int n = cnt;
    float acc = 0.f;
    for (int k = 0; k < n; k++) acc += colemb[(int)nz[k] * DD + t];
    x0[i * DD + t] = (n > 0) ? acc / (float)n : 0.f;
}

// ---------------- per-branch graph prep ----------------
__global__ void branch_init(float* __restrict__ deg, int* __restrict__ hist) {
    int i = blockIdx.x * blockDim.x + threadIdx.x;
    if (i < NNODES) { deg[i] = 1.0f; hist[i] = 0; }
}

__global__ void edge_count(const int* __restrict__ ei, const float* __restrict__ ea,
                           float* __restrict__ deg, int* __restrict__ hist) {
    int e = blockIdx.x * blockDim.x + threadIdx.x;
    if (e < NEDGE) {
        int c = ei[NEDGE + e];
        atomicAdd(&deg[c], ea[e]);
        atomicAdd(&hist[c], 1);
    }
}

__global__ void dinv_kernel(const float* __restrict__ deg, float* __restrict__ dinv) {
    int i = blockIdx.x * blockDim.x + threadIdx.x;
    if (i < NNODES) dinv[i] = rsqrtf(deg[i]);
}

__global__ void scan_kernel(const int* __restrict__ hist, int* __restrict__ start,
                            int* __restrict__ cur) {
    __shared__ int sm[1024];
    __shared__ int carry_s;
    int t = threadIdx.x;
    if (t == 0) carry_s = 0;
    __syncthreads();
    for (int c0 = 0; c0 < NNODES; c0 += 1024) {
        int idx = c0 + t;
        int v = (idx < NNODES) ? hist[idx] : 0;
        sm[t] = v;
        __syncthreads();
        for (int off = 1; off < 1024; off <<= 1) {
            int x = (t >= off) ? sm[t - off] : 0;
            __syncthreads();
            sm[t] += x;
            __syncthreads();
        }
        int incl = sm[t];
        int base = carry_s;
        __syncthreads();
        if (t == 1023) carry_s = base + incl;
        int excl = base + incl - v;
        if (idx < NNODES) { start[idx] = excl; cur[idx] = excl; }
        __syncthreads();
    }
    if (t == 0) start[NNODES] = carry_s;
}

__global__ void scatter_kernel(const int* __restrict__ ei, const float* __restrict__ ea,
                               const float* __restrict__ dinv, int* __restrict__ cur,
                               int* __restrict__ src, float* __restrict__ nrm) {
    int e = blockIdx.x * blockDim.x + threadIdx.x;
    if (e < NEDGE) {
        int r = ei[e];
        int c = ei[NEDGE + e];
        float n = dinv[r] * ea[e] * dinv[c];
        int p = atomicAdd(&cur[c], 1);
        src[p] = r;
        nrm[p] = n;
    }
}

// ================= split-bf16 HMMA GEMM =================
// C[NPAD,256] = act(A)[NPAD,256] @ W[256,256]  (W row-major [K,N])
// CTA tile 128(M)x128(N), K=256 chunked by 32. 8 warps = 2(M) x 4(N); each
// warp computes 64x32 as 4x4 m16n8k16 tiles. Split bf16: A=Ah+Al, W=Wh+Wl;
// acc += Ah*Wh + Al*Wh + Ah*Wl  (fp32-grade precision).
#define KC 32
#define APITCH 20      // uint32 words per smem row (16 pairs + 4 pad) — conflict-free

__device__ __forceinline__ void mma_bf16(float* c, const uint32_t* a, const uint32_t* b) {
    asm volatile(
        "mma.sync.aligned.m16n8k16.row.col.f32.bf16.bf16.f32 "
        "{%0,%1,%2,%3}, {%4,%5,%6,%7}, {%8,%9}, {%0,%1,%2,%3};"
        : "+f"(c[0]), "+f"(c[1]), "+f"(c[2]), "+f"(c[3])
        : "r"(a[0]), "r"(a[1]), "r"(a[2]), "r"(a[3]), "r"(b[0]), "r"(b[1]));
}

__device__ __forceinline__ uint32_t pack_hi(float x, float y) {
    __nv_bfloat162 h;
    h.x = __float2bfloat16(x);
    h.y = __float2bfloat16(y);
    return *reinterpret_cast<uint32_t*>(&h);
}
__device__ __forceinline__ uint32_t pack_lo(float x, float y, uint32_t hi) {
    __nv_bfloat162 h = *reinterpret_cast<__nv_bfloat162*>(&hi);
    __nv_bfloat162 l;
    l.x = __float2bfloat16(x - __bfloat162float(h.x));
    l.y = __float2bfloat16(y - __bfloat162float(h.y));
    return *reinterpret_cast<uint32_t*>(&l);
}

__global__ void __launch_bounds__(256, 2) gemm_mma(const float* __restrict__ A,
                                                   const float* __restrict__ W,
                                                   float* __restrict__ C, int relu_in) {
    __shared__ uint32_t sAh[128 * APITCH];
    __shared__ uint32_t sAl[128 * APITCH];
    __shared__ uint32_t sBh[128 * APITCH];   // stored [n][k-pair]
    __shared__ uint32_t sBl[128 * APITCH];

    int tid = threadIdx.x;
    int wid = tid >> 5;
    int lane = tid & 31;
    int g = lane >> 2;          // group row 0..7
    int tig = lane & 3;         // thread-in-group
    int wm = wid & 1;           // 0..1 -> 64-row band
    int wn = wid >> 1;          // 0..3 -> 32-col band
    int bm = blockIdx.x * 128;
    int bn = blockIdx.y * 128;

    float acc[4][4][4];
#pragma unroll
    for (int mt = 0; mt < 4; mt++)
#pragma unroll
        for (int nt = 0; nt < 4; nt++)
#pragma unroll
            for (int q = 0; q < 4; q++) acc[mt][nt][q] = 0.f;

    for (int k0 = 0; k0 < DD; k0 += KC) {
        // ---- A chunk: 128 rows x 32 cols = 1024 float4
#pragma unroll
        for (int i = 0; i < 4; i++) {
            int idx = tid + i * 256;
            int row = idx >> 3;
            int q = idx & 7;
            float4 v = *(const float4*)&A[(size_t)(bm + row) * DD + k0 + q * 4];
            if (relu_in) {
                v.x = fmaxf(v.x, 0.f); v.y = fmaxf(v.y, 0.f);
                v.z = fmaxf(v.z, 0.f); v.w = fmaxf(v.w, 0.f);
            }
            uint32_t h01 = pack_hi(v.x, v.y);
            uint32_t h23 = pack_hi(v.z, v.w);
            sAh[row * APITCH + q * 2]     = h01;
            sAh[row * APITCH + q * 2 + 1] = h23;
            sAl[row * APITCH + q * 2]     = pack_lo(v.x, v.y, h01);
            sAl[row * APITCH + q * 2 + 1] = pack_lo(v.z, v.w, h23);
        }
        // ---- B chunk: W[k0..k0+31][bn..bn+127] -> [n][kpair]; 512 units
#pragma unroll
        for (int i = 0; i < 2; i++) {
            int u = tid + i * 256;
            int kp = u & 15;
            int n4 = u >> 4;
            const float4 v0 = *(const float4*)&W[(size_t)(k0 + 2 * kp) * DD + bn + n4 * 4];
            const float4 v1 = *(const float4*)&W[(size_t)(k0 + 2 * kp + 1) * DD + bn + n4 * 4];
            float a0[4] = {v0.x, v0.y, v0.z, v0.w};
            float a1[4] = {v1.x, v1.y, v1.z, v1.w};
#pragma unroll
            for (int j = 0; j < 4; j++) {
                uint32_t h = pack_hi(a0[j], a1[j]);
                int n = n4 * 4 + j;
                sBh[n * APITCH + kp] = h;
                sBl[n * APITCH + kp] = pack_lo(a0[j], a1[j], h);
            }
        }
        __syncthreads();

#pragma unroll
        for (int ks = 0; ks < 2; ks++) {
            int kb = ks * 8 + tig;
            uint32_t Bh[4][2], Bl[4][2];
#pragma unroll
            for (int nt = 0; nt < 4; nt++) {
                int n = wn * 32 + nt * 8 + g;
                Bh[nt][0] = sBh[n * APITCH + kb];
                Bh[nt][1] = sBh[n * APITCH + kb + 4];
                Bl[nt][0] = sBl[n * APITCH + kb];
                Bl[nt][1] = sBl[n * APITCH + kb + 4];
            }
#pragma unroll
            for (int mt = 0; mt < 4; mt++) {
                int r0 = wm * 64 + mt * 16 + g;
                uint32_t Ah[4], Al[4];
                Ah[0] = sAh[r0 * APITCH + kb];
                Ah[1] = sAh[(r0 + 8) * APITCH + kb];
                Ah[2] = sAh[r0 * APITCH + kb + 4];
                Ah[3] = sAh[(r0 + 8) * APITCH + kb + 4];
                Al[0] = sAl[r0 * APITCH + kb];
                Al[1] = sAl[(r0 + 8) * APITCH + kb];
                Al[2] = sAl[r0 * APITCH + kb + 4];
                Al[3] = sAl[(r0 + 8) * APITCH + kb + 4];
#pragma unroll
                for (int nt = 0; nt < 4; nt++) {
                    mma_bf16(acc[mt][nt], Ah, Bh[nt]);
                    mma_bf16(acc[mt][nt], Al, Bh[nt]);
                    mma_bf16(acc[mt][nt], Ah, Bl[nt]);
                }
            }
        }
        __syncthreads();
    }

    // ---- epilogue
#pragma unroll
    for (int mt = 0; mt < 4; mt++) {
        int row = bm + wm * 64 + mt * 16 + g;
#pragma unroll
        for (int nt = 0; nt < 4; nt++) {
            int col = bn + wn * 32 + nt * 8 + tig * 2;
            float2 v0 = make_float2(acc[mt][nt][0], acc[mt][nt][1]);
            float2 v1 = make_float2(acc[mt][nt][2], acc[mt][nt][3]);
            *(float2*)&C[(size_t)row * DD + col] = v0;
            *(float2*)&C[(size_t)(row + 8) * DD + col] = v1;
        }
    }
}

// ---------------- aggregation ----------------
__global__ void __launch_bounds__(64) agg_kernel(const float* __restrict__ h, const int* __restrict__ src,
                           const float* __restrict__ nrm, const int* __restrict__ start,
                           const float* __restrict__ dinv, const float* __restrict__ bias,
                           float* __restrict__ out) {
    int i = blockIdx.x;
    int t = threadIdx.x;  // 64, float4 each
    int s = start[i];
    int e = start[i + 1];
    float4 a0 = make_float4(0.f, 0.f, 0.f, 0.f);
    float4 a1 = make_float4(0.f, 0.f, 0.f, 0.f);
    float4 a2 = make_float4(0.f, 0.f, 0.f, 0.f);
    float4 a3 = make_float4(0.f, 0.f, 0.f, 0.f);
    int k = s;
    for (; k + 3 < e; k += 4) {
        int r0 = src[k], r1 = src[k + 1], r2 = src[k + 2], r3 = src[k + 3];
        float w0 = nrm[k], w1 = nrm[k + 1], w2 = nrm[k + 2], w3 = nrm[k + 3];
        float4 v0 = *(const float4*)&h[(size_t)r0 * DD + t * 4];
        float4 v1 = *(const float4*)&h[(size_t)r1 * DD + t * 4];
        float4 v2 = *(const float4*)&h[(size_t)r2 * DD + t * 4];
        float4 v3 = *(const float4*)&h[(size_t)r3 * DD + t * 4];
        a0.x += w0 * v0.x; a0.y += w0 * v0.y; a0.z += w0 * v0.z; a0.w += w0 * v0.w;
        a1.x += w1 * v1.x; a1.y += w1 * v1.y; a1.z += w1 * v1.z; a1.w += w1 * v1.w;
        a2.x += w2 * v2.x; a2.y += w2 * v2.y; a2.z += w2 * v2.z; a2.w += w2 * v2.w;
        a3.x += w3 * v3.x; a3.y += w3 * v3.y; a3.z += w3 * v3.z; a3.w += w3 * v3.w;
    }
    for (; k < e; k++) {
        int r = src[k];
        float w = nrm[k];
        float4 v = *(const float4*)&h[(size_t)r * DD + t * 4];
        a0.x += w * v.x; a0.y += w * v.y; a0.z += w * v.z; a0.w += w * v.w;
    }
    float di = dinv[i];
    float sn = di * di;
    float4 hv = *(const float4*)&h[(size_t)i * DD + t * 4];
    float4 bv = *(const float4*)&bias[t * 4];
    float4 acc;
    acc.x = a0.x + a1.x + a2.x + a3.x + sn * hv.x + bv.x;
    acc.y = a0.y + a1.y + a2.y + a3.y + sn * hv.y + bv.y;
    acc.z = a0.z + a1.z + a2.z + a3.z + sn * hv.z + bv.z;
    acc.w = a0.w + a1.w + a2.w + a3.w + sn * hv.w + bv.w;
    *(float4*)&out[(size_t)i * DD + t * 4] = acc;
}

// ---------------- meta-path attention ----------------
__global__ void attn_kernel(const float* __restrict__ b0, const float* __restrict__ b1,
                            const float* __restrict__ b2, const float* __restrict__ watt,
                            float* __restrict__ out) {
    int i = blockIdx.x;
    int t = threadIdx.x;  // 256
    size_t off = (size_t)i * DD + t;
    float x0v = fmaxf(b0[off], 0.f);
    float x1v = fmaxf(b1[off], 0.f);
    float x2v = fmaxf(b2[off], 0.f);
    float w = watt[t];
    float s0 = x0v * w, s1 = x1v * w, s2 = x2v * w;
#pragma unroll
    for (int o = 16; o; o >>= 1) {
        s0 += __shfl_xor_sync(0xffffffffu, s0, o);
        s1 += __shfl_xor_sync(0xffffffffu, s1, o);
        s2 += __shfl_xor_sync(0xffffffffu, s2, o);
    }
    __shared__ float sm[3][8];
    __shared__ float sw[3];
    int wid = t >> 5, ln = t & 31;
    if (ln == 0) { sm[0][wid] = s0; sm[1][wid] = s1; sm[2][wid] = s2; }
    __syncthreads();
    if (t == 0) {
        float t0 = 0.f, t1 = 0.f, t2 = 0.f;
#pragma unroll
        for (int kk = 0; kk < 8; kk++) { t0 += sm[0][kk]; t1 += sm[1][kk]; t2 += sm[2][kk]; }
        float mx = fmaxf(t0, fmaxf(t1, t2));
        float e0 = expf(t0 - mx), e1 = expf(t1 - mx), e2 = expf(t2 - mx);
        float inv = 1.f / (e0 + e1 + e2);
        sw[0] = e0 * inv; sw[1] = e1 * inv; sw[2] = e2 * inv;
    }
    __syncthreads();
    out[off] = sw[0] * x0v + sw[1] * x1v + sw[2] * x2v;
}

// ---------------- launcher ----------------
extern "C" void kernel_launch(void* const* d_in, const int* in_sizes, int n_in,
                              void* d_out, int out_size) {
    const float* init = (const float*)d_in[0];
    const int*   ei[3] = {(const int*)d_in[1], (const int*)d_in[2], (const int*)d_in[3]};
    const float* ea[3] = {(const float*)d_in[4], (const float*)d_in[5], (const float*)d_in[6]};
    const float* pW1 = (const float*)d_in[7];
    const float* pb1 = (const float*)d_in[8];
    const float* pW2 = (const float*)d_in[9];
    const float* pb2 = (const float*)d_in[10];
    const float* Wb[3] = {(const float*)d_in[11], (const float*)d_in[13], (const float*)d_in[15]};
    const float* bb[3] = {(const float*)d_in[12], (const float*)d_in[14], (const float*)d_in[16]};
    const float* watt = (const float*)d_in[17];
    float* out = (float*)d_out;

    float *colemb, *x0, *h, *bufA, *bufB, *deg, *dinv, *nrm;
    float *br[3];
    int *hist, *cur, *start, *src;
    cudaGetSymbolAddress((void**)&colemb, g_colemb);
    cudaGetSymbolAddress((void**)&x0,     g_x0);
    cudaGetSymbolAddress((void**)&h,      g_h);
    cudaGetSymbolAddress((void**)&bufA,   g_bufA);
    cudaGetSymbolAddress((void**)&bufB,   g_bufB);
    cudaGetSymbolAddress((void**)&br[0],  g_br0);
    cudaGetSymbolAddress((void**)&br[1],  g_br1);
    cudaGetSymbolAddress((void**)&br[2],  g_br2);
    cudaGetSymbolAddress((void**)&deg,    g_deg);
    cudaGetSymbolAddress((void**)&dinv,   g_dinv);
    cudaGetSymbolAddress((void**)&hist,   g_hist);
    cudaGetSymbolAddress((void**)&cur,    g_cur);
    cudaGetSymbolAddress((void**)&start,  g_start);
    cudaGetSymbolAddress((void**)&src,    g_src);
    cudaGetSymbolAddress((void**)&nrm,    g_nrm);

    colemb_kernel<<<MCOLS, DD>>>(pW1, pb1, pW2, pb2, colemb);
    x0_kernel<<<NNODES, 256>>>(init, colemb, x0);

    const int NB = (NNODES + 255) / 256;
    const int EB = (NEDGE + 255) / 256;

    for (int b = 0; b < 3; b++) {
        branch_init<<<NB, 256>>>(deg, hist);
        edge_count<<<EB, 256>>>(ei[b], ea[b], deg, hist);
        dinv_kernel<<<NB, 256>>>(deg, dinv);
        scan_kernel<<<1, 1024>>>(hist, start, cur);
        scatter_kernel<<<EB, 256>>>(ei[b], ea[b], dinv, cur, src, nrm);

        const float* x = x0;
        float* outs[3] = {bufA, bufB, br[b]};
        for (int l = 0; l < 3; l++) {
            gemm_mma<<<dim3(NPAD / 128, 2), 256>>>(x, Wb[b] + (size_t)l * DD * DD, h, l > 0);
            agg_kernel<<<NNODES, 64>>>(h, src, nrm, start, dinv, bb[b] + l * DD, outs[l]);
            x = outs[l];
        }
    }

    attn_kernel<<<NNODES, 256>>>(br[0], br[1], br[2], watt, out);
}

// round 4
// speedup vs baseline: 1.3786x; 1.1617x over previous
#include <cuda_runtime.h>
#include <cuda_bf16.h>
#include <cstdint>

#define NNODES 20000
#define NPAD   20096            // 157 * 128
#define MCOLS  1024
#define NEDGE  640000
#define DD     256

// ---------------- scratch (__device__ globals; zero-initialized bss) ----------------
__device__ float g_colemb[MCOLS * DD];
__device__ float g_x0[NPAD * DD];
__device__ float g_h[NPAD * DD];
__device__ float g_br0[NPAD * DD];
__device__ float g_br1[NPAD * DD];
__device__ float g_br2[NPAD * DD];
__device__ float g_deg[NNODES];
__device__ float g_dinv[NNODES];
__device__ int   g_hist[NNODES];
__device__ int   g_cur[NNODES];
__device__ int   g_start[NNODES + 1];
__device__ int   g_src[NEDGE];
__device__ float g_nrm[NEDGE];
// packed bf16 hi/lo planes (A operands), k-contiguous rows of 256
__device__ __nv_bfloat16 g_x0h[NPAD * DD];
__device__ __nv_bfloat16 g_x0l[NPAD * DD];
__device__ __nv_bfloat16 g_xh[NPAD * DD];
__device__ __nv_bfloat16 g_xl[NPAD * DD];
// transposed bf16 hi/lo weights: [9][n=256][k=256]
__device__ __nv_bfloat16 g_Wh[9 * DD * DD];
__device__ __nv_bfloat16 g_Wl[9 * DD * DD];

// ---------------- projection: col_emb ----------------
__global__ void colemb_kernel(const float* __restrict__ pW1, const float* __restrict__ pb1,
                              const float* __restrict__ pW2, const float* __restrict__ pb2,
                              float* __restrict__ colemb) {
    int j = blockIdx.x;
    int d = threadIdx.x;
    float jf = (float)j;
    float acc = pb2[d];
#pragma unroll
    for (int k = 0; k < 16; k++) {
        float hk = fmaxf(jf * pW1[k] + pb1[k], 0.f);
        acc += hk * pW2[k * DD + d];
    }
    colemb[j * DD + d] = acc;
}

// ---------------- x0: masked mean over nonzero cols (+ bf16 hi/lo pack) ----------------
__global__ void x0_kernel(const float* __restrict__ init, const float* __restrict__ colemb,
                          float* __restrict__ x0,
                          __nv_bfloat16* __restrict__ xh, __nv_bfloat16* __restrict__ xl) {
    int i = blockIdx.x;
    int t = threadIdx.x;  // 256
    __shared__ unsigned short nz[MCOLS];
    __shared__ int cnt;
    if (t == 0) cnt = 0;
    __syncthreads();
    const float* row = init + (size_t)i * MCOLS;
    for (int c = t; c < MCOLS; c += 256) {
        if (row[c] != 0.f) {
            int p = atomicAdd(&cnt, 1);
            nz[p] = (unsigned short)c;
        }
    }
    __syncthreads();
    int n = cnt;
    float acc = 0.f;
    for (int k = 0; k < n; k++) acc += colemb[(int)nz[k] * DD + t];
    float v = (n > 0) ? acc / (float)n : 0.f;
    size_t off = (size_t)i * DD + t;
    x0[off] = v;
    __nv_bfloat16 h = __float2bfloat16(v);
    xh[off] = h;
    xl[off] = __float2bfloat16(v - __bfloat162float(h));
}

// ---------------- weight convert: Wt_hi/lo[n][k] = bf16split(W[k][n]) ----------------
__global__ void wconv_kernel(const float* __restrict__ W,
                             __nv_bfloat16* __restrict__ Ht, __nv_bfloat16* __restrict__ Lt) {
    __shared__ float tile[32][33];
    int n0 = blockIdx.x * 32, k0 = blockIdx.y * 32;
    int tx = threadIdx.x, ty = threadIdx.y;  // 32 x 8
#pragma unroll
    for (int i = 0; i < 32; i += 8) tile[ty + i][tx] = W[(size_t)(k0 + ty + i) * DD + n0 + tx];
    __syncthreads();
#pragma unroll
    for (int i = 0; i < 32; i += 8) {
        float v = tile[tx][ty + i];                 // W[k0+tx][n0+ty+i]
        __nv_bfloat16 h = __float2bfloat16(v);
        size_t o = (size_t)(n0 + ty + i) * DD + k0 + tx;
        Ht[o] = h;
        Lt[o] = __float2bfloat16(v - __bfloat162float(h));
    }
}

// ---------------- per-branch graph prep ----------------
__global__ void branch_init(float* __restrict__ deg, int* __restrict__ hist) {
    int i = blockIdx.x * blockDim.x + threadIdx.x;
    if (i < NNODES) { deg[i] = 1.0f; hist[i] = 0; }
}

__global__ void edge_count(const int* __restrict__ ei, const float* __restrict__ ea,
                           float* __restrict__ deg, int* __restrict__ hist) {
    int e = blockIdx.x * blockDim.x + threadIdx.x;
    if (e < NEDGE) {
        int c = ei[NEDGE + e];
        atomicAdd(&deg[c], ea[e]);
        atomicAdd(&hist[c], 1);
    }
}

__global__ void dinv_kernel(const float* __restrict__ deg, float* __restrict__ dinv) {
    int i = blockIdx.x * blockDim.x + threadIdx.x;
    if (i < NNODES) dinv[i] = rsqrtf(deg[i]);
}

__global__ void scan_kernel(const int* __restrict__ hist, int* __restrict__ start,
                            int* __restrict__ cur) {
    __shared__ int sm[1024];
    __shared__ int carry_s;
    int t = threadIdx.x;
    if (t == 0) carry_s = 0;
    __syncthreads();
    for (int c0 = 0; c0 < NNODES; c0 += 1024) {
        int idx = c0 + t;
        int v = (idx < NNODES) ? hist[idx] : 0;
        sm[t] = v;
        __syncthreads();
        for (int off = 1; off < 1024; off <<= 1) {
            int x = (t >= off) ? sm[t - off] : 0;
            __syncthreads();
            sm[t] += x;
            __syncthreads();
        }
        int incl = sm[t];
        int base = carry_s;
        __syncthreads();
        if (t == 1023) carry_s = base + incl;
        int excl = base + incl - v;
        if (idx < NNODES) { start[idx] = excl; cur[idx] = excl; }
        __syncthreads();
    }
    if (t == 0) start[NNODES] = carry_s;
}

__global__ void scatter_kernel(const int* __restrict__ ei, const float* __restrict__ ea,
                               const float* __restrict__ dinv, int* __restrict__ cur,
                               int* __restrict__ src, float* __restrict__ nrm) {
    int e = blockIdx.x * blockDim.x + threadIdx.x;
    if (e < NEDGE) {
        int r = ei[e];
        int c = ei[NEDGE + e];
        float n = dinv[r] * ea[e] * dinv[c];
        int p = atomicAdd(&cur[c], 1);
        src[p] = r;
        nrm[p] = n;
    }
}

// ================= split-bf16 HMMA GEMM (preconverted operands) =================
// C[NPAD,256] = A @ W,  A given as bf16 hi/lo planes [row][k], W as bf16 hi/lo [n][k].
// CTA tile 128(M)x128(N), K chunked by 64. 8 warps = 2(M) x 4(N), each warp 64x32
// via 4x4 m16n8k16 tiles. acc += Ah*Wh + Al*Wh + Ah*Wl.
#define KC 64
#define PITCH 36      // uint32 words per smem row (32 kpairs + 4 pad) — conflict-free

__device__ __forceinline__ void mma_bf16(float* c, const uint32_t* a, const uint32_t* b) {
    asm volatile(
        "mma.sync.aligned.m16n8k16.row.col.f32.bf16.bf16.f32 "
        "{%0,%1,%2,%3}, {%4,%5,%6,%7}, {%8,%9}, {%0,%1,%2,%3};"
        : "+f"(c[0]), "+f"(c[1]), "+f"(c[2]), "+f"(c[3])
        : "r"(a[0]), "r"(a[1]), "r"(a[2]), "r"(a[3]), "r"(b[0]), "r"(b[1]));
}
__device__ __forceinline__ void cp16(uint32_t smem_dst, const void* gsrc) {
    asm volatile("cp.async.cg.shared.global [%0], [%1], 16;" :: "r"(smem_dst), "l"(gsrc));
}

__global__ void __launch_bounds__(256, 2) gemm_mma2(
    const __nv_bfloat16* __restrict__ Ah_g, const __nv_bfloat16* __restrict__ Al_g,
    const __nv_bfloat16* __restrict__ Bh_g, const __nv_bfloat16* __restrict__ Bl_g,
    float* __restrict__ C) {
    extern __shared__ uint32_t smem[];
    uint32_t* sAh = smem;
    uint32_t* sAl = smem + 128 * PITCH;
    uint32_t* sBh = smem + 2 * 128 * PITCH;
    uint32_t* sBl = smem + 3 * 128 * PITCH;

    int tid = threadIdx.x;
    int lane = tid & 31, wid = tid >> 5;
    int g = lane >> 2, tig = lane & 3;
    int wm = wid & 1, wn = wid >> 1;
    int bm = blockIdx.x * 128;
    int bn = blockIdx.y * 128;

    uint32_t sAh_a = (uint32_t)__cvta_generic_to_shared(sAh);
    uint32_t sAl_a = (uint32_t)__cvta_generic_to_shared(sAl);
    uint32_t sBh_a = (uint32_t)__cvta_generic_to_shared(sBh);
    uint32_t sBl_a = (uint32_t)__cvta_generic_to_shared(sBl);

    float acc[4][4][4];
#pragma unroll
    for (int mt = 0; mt < 4; mt++)
#pragma unroll
        for (int nt = 0; nt < 4; nt++)
#pragma unroll
            for (int q = 0; q < 4; q++) acc[mt][nt][q] = 0.f;

    for (int k0 = 0; k0 < DD; k0 += KC) {
        // ---- async loads: each array is 128 rows x 8 segs(16B); 4 segs/thread/array
#pragma unroll
        for (int i = 0; i < 4; i++) {
            int sl = tid + i * 256;
            int row = sl >> 3;
            int s = sl & 7;
            uint32_t so = (uint32_t)(row * PITCH + s * 4) * 4u;
            size_t ga = (size_t)(bm + row) * DD + k0 + s * 8;
            size_t gb = (size_t)(bn + row) * DD + k0 + s * 8;
            cp16(sAh_a + so, Ah_g + ga);
            cp16(sAl_a + so, Al_g + ga);
            cp16(sBh_a + so, Bh_g + gb);
            cp16(sBl_a + so, Bl_g + gb);
        }
        asm volatile("cp.async.commit_group;");
        asm volatile("cp.async.wait_group 0;");
        __syncthreads();

#pragma unroll
        for (int ks = 0; ks < 4; ks++) {
            int kb = ks * 8 + tig;
            uint32_t Bh[4][2], Bl[4][2];
#pragma unroll
            for (int nt = 0; nt < 4; nt++) {
                int n = wn * 32 + nt * 8 + g;
                Bh[nt][0] = sBh[n * PITCH + kb];
                Bh[nt][1] = sBh[n * PITCH + kb + 4];
                Bl[nt][0] = sBl[n * PITCH + kb];
                Bl[nt][1] = sBl[n * PITCH + kb + 4];
            }
#pragma unroll
            for (int mt = 0; mt < 4; mt++) {
                int r0 = wm * 64 + mt * 16 + g;
                uint32_t Ah[4], Al[4];
                Ah[0] = sAh[r0 * PITCH + kb];
                Ah[1] = sAh[(r0 + 8) * PITCH + kb];
                Ah[2] = sAh[r0 * PITCH + kb + 4];
                Ah[3] = sAh[(r0 + 8) * PITCH + kb + 4];
                Al[0] = sAl[r0 * PITCH + kb];
                Al[1] = sAl[(r0 + 8) * PITCH + kb];
                Al[2] = sAl[r0 * PITCH + kb + 4];
                Al[3] = sAl[(r0 + 8) * PITCH + kb + 4];
#pragma unroll
                for (int nt = 0; nt < 4; nt++) {
                    mma_bf16(acc[mt][nt], Ah, Bh[nt]);
                    mma_bf16(acc[mt][nt], Al, Bh[nt]);
                    mma_bf16(acc[mt][nt], Ah, Bl[nt]);
                }
            }
        }
        __syncthreads();
    }

    // ---- epilogue
#pragma unroll
    for (int mt = 0; mt < 4; mt++) {
        int row = bm + wm * 64 + mt * 16 + g;
#pragma unroll
        for (int nt = 0; nt < 4; nt++) {
            int col = bn + wn * 32 + nt * 8 + tig * 2;
            *(float2*)&C[(size_t)row * DD + col] = make_float2(acc[mt][nt][0], acc[mt][nt][1]);
            *(float2*)&C[(size_t)(row + 8) * DD + col] = make_float2(acc[mt][nt][2], acc[mt][nt][3]);
        }
    }
}

// ---------------- aggregation (+ optional relu'd bf16 hi/lo pack for next layer) --------
__global__ void __launch_bounds__(64) agg_kernel(const float* __restrict__ h, const int* __restrict__ src,
                           const float* __restrict__ nrm, const int* __restrict__ start,
                           const float* __restrict__ dinv, const float* __restrict__ bias,
                           float* __restrict__ out,
                           __nv_bfloat16* __restrict__ xh, __nv_bfloat16* __restrict__ xl,
                           int pack, int wf32) {
    int i = blockIdx.x;
    int t = threadIdx.x;  // 64, float4 each
    int s = start[i];
    int e = start[i + 1];
    float4 a0 = make_float4(0.f, 0.f, 0.f, 0.f);
    float4 a1 = make_float4(0.f, 0.f, 0.f, 0.f);
    float4 a2 = make_float4(0.f, 0.f, 0.f, 0.f);
    float4 a3 = make_float4(0.f, 0.f, 0.f, 0.f);
    int k = s;
    for (; k + 3 < e; k += 4) {
        int r0 = src[k], r1 = src[k + 1], r2 = src[k + 2], r3 = src[k + 3];
        float w0 = nrm[k], w1 = nrm[k + 1], w2 = nrm[k + 2], w3 = nrm[k + 3];
        float4 v0 = *(const float4*)&h[(size_t)r0 * DD + t * 4];
        float4 v1 = *(const float4*)&h[(size_t)r1 * DD + t * 4];
        float4 v2 = *(const float4*)&h[(size_t)r2 * DD + t * 4];
        float4 v3 = *(const float4*)&h[(size_t)r3 * DD + t * 4];
        a0.x += w0 * v0.x; a0.y += w0 * v0.y; a0.z += w0 * v0.z; a0.w += w0 * v0.w;
        a1.x += w1 * v1.x; a1.y += w1 * v1.y; a1.z += w1 * v1.z; a1.w += w1 * v1.w;
        a2.x += w2 * v2.x; a2.y += w2 * v2.y; a2.z += w2 * v2.z; a2.w += w2 * v2.w;
        a3.x += w3 * v3.x; a3.y += w3 * v3.y; a3.z += w3 * v3.z; a3.w += w3 * v3.w;
    }
    for (; k < e; k++) {
        int r = src[k];
        float w = nrm[k];
        float4 v = *(const float4*)&h[(size_t)r * DD + t * 4];
        a0.x += w * v.x; a0.y += w * v.y; a0.z += w * v.z; a0.w += w * v.w;
    }
    float di = dinv[i];
    float sn = di * di;
    float4 hv = *(const float4*)&h[(size_t)i * DD + t * 4];
    float4 bv = *(const float4*)&bias[t * 4];
    float4 acc;
    acc.x = a0.x + a1.x + a2.x + a3.x + sn * hv.x + bv.x;
    acc.y = a0.y + a1.y + a2.y + a3.y + sn * hv.y + bv.y;
    acc.z = a0.z + a1.z + a2.z + a3.z + sn * hv.z + bv.z;
    acc.w = a0.w + a1.w + a2.w + a3.w + sn * hv.w + bv.w;
    if (wf32) *(float4*)&out[(size_t)i * DD + t * 4] = acc;
    if (pack) {
        float r0 = fmaxf(acc.x, 0.f), r1 = fmaxf(acc.y, 0.f);
        float r2 = fmaxf(acc.z, 0.f), r3 = fmaxf(acc.w, 0.f);
        __nv_bfloat162 h01, h23, l01, l23;
        h01.x = __float2bfloat16(r0); h01.y = __float2bfloat16(r1);
        h23.x = __float2bfloat16(r2); h23.y = __float2bfloat16(r3);
        l01.x = __float2bfloat16(r0 - __bfloat162float(h01.x));
        l01.y = __float2bfloat16(r1 - __bfloat162float(h01.y));
        l23.x = __float2bfloat16(r2 - __bfloat162float(h23.x));
        l23.y = __float2bfloat16(r3 - __bfloat162float(h23.y));
        uint2 hp, lp;
        hp.x = *reinterpret_cast<uint32_t*>(&h01);
        hp.y = *reinterpret_cast<uint32_t*>(&h23);
        lp.x = *reinterpret_cast<uint32_t*>(&l01);
        lp.y = *reinterpret_cast<uint32_t*>(&l23);
        reinterpret_cast<uint2*>(xh)[(size_t)i * 64 + t] = hp;
        reinterpret_cast<uint2*>(xl)[(size_t)i * 64 + t] = lp;
    }
}

// ---------------- meta-path attention ----------------
__global__ void attn_kernel(const float* __restrict__ b0, const float* __restrict__ b1,
                            const float* __restrict__ b2, const float* __restrict__ watt,
                            float* __restrict__ out) {
    int i = blockIdx.x;
    int t = threadIdx.x;  // 256
    size_t off = (size_t)i * DD + t;
    float x0v = fmaxf(b0[off], 0.f);
    float x1v = fmaxf(b1[off], 0.f);
    float x2v = fmaxf(b2[off], 0.f);
    float w = watt[t];
    float s0 = x0v * w, s1 = x1v * w, s2 = x2v * w;
#pragma unroll
    for (int o = 16; o; o >>= 1) {
        s0 += __shfl_xor_sync(0xffffffffu, s0, o);
        s1 += __shfl_xor_sync(0xffffffffu, s1, o);
        s2 += __shfl_xor_sync(0xffffffffu, s2, o);
    }
    __shared__ float sm[3][8];
    __shared__ float sw[3];
    int wid = t >> 5, ln = t & 31;
    if (ln == 0) { sm[0][wid] = s0; sm[1][wid] = s1; sm[2][wid] = s2; }
    __syncthreads();
    if (t == 0) {
        float t0 = 0.f, t1 = 0.f, t2 = 0.f;
#pragma unroll
        for (int kk = 0; kk < 8; kk++) { t0 += sm[0][kk]; t1 += sm[1][kk]; t2 += sm[2][kk]; }
        float mx = fmaxf(t0, fmaxf(t1, t2));
        float e0 = expf(t0 - mx), e1 = expf(t1 - mx), e2 = expf(t2 - mx);
        float inv = 1.f / (e0 + e1 + e2);
        sw[0] = e0 * inv; sw[1] = e1 * inv; sw[2] = e2 * inv;
    }
    __syncthreads();
    out[off] = sw[0] * x0v + sw[1] * x1v + sw[2] * x2v;
}

// ---------------- launcher ----------------
extern "C" void kernel_launch(void* const* d_in, const int* in_sizes, int n_in,
                              void* d_out, int out_size) {
    const float* init = (const float*)d_in[0];
    const int*   ei[3] = {(const int*)d_in[1], (const int*)d_in[2], (const int*)d_in[3]};
    const float* ea[3] = {(const float*)d_in[4], (const float*)d_in[5], (const float*)d_in[6]};
    const float* pW1 = (const float*)d_in[7];
    const float* pb1 = (const float*)d_in[8];
    const float* pW2 = (const float*)d_in[9];
    const float* pb2 = (const float*)d_in[10];
    const float* Wb[3] = {(const float*)d_in[11], (const float*)d_in[13], (const float*)d_in[15]};
    const float* bb[3] = {(const float*)d_in[12], (const float*)d_in[14], (const float*)d_in[16]};
    const float* watt = (const float*)d_in[17];
    float* out = (float*)d_out;

    float *colemb, *x0, *h, *deg, *dinv, *nrm;
    float *br[3];
    int *hist, *cur, *start, *src;
    __nv_bfloat16 *x0h, *x0l, *xh, *xl, *Wh, *Wl;
    cudaGetSymbolAddress((void**)&colemb, g_colemb);
    cudaGetSymbolAddress((void**)&x0,     g_x0);
    cudaGetSymbolAddress((void**)&h,      g_h);
    cudaGetSymbolAddress((void**)&br[0],  g_br0);
    cudaGetSymbolAddress((void**)&br[1],  g_br1);
    cudaGetSymbolAddress((void**)&br[2],  g_br2);
    cudaGetSymbolAddress((void**)&deg,    g_deg);
    cudaGetSymbolAddress((void**)&dinv,   g_dinv);
    cudaGetSymbolAddress((void**)&hist,   g_hist);
    cudaGetSymbolAddress((void**)&cur,    g_cur);
    cudaGetSymbolAddress((void**)&start,  g_start);
    cudaGetSymbolAddress((void**)&src,    g_src);
    cudaGetSymbolAddress((void**)&nrm,    g_nrm);
    cudaGetSymbolAddress((void**)&x0h,    g_x0h);
    cudaGetSymbolAddress((void**)&x0l,    g_x0l);
    cudaGetSymbolAddress((void**)&xh,     g_xh);
    cudaGetSymbolAddress((void**)&xl,     g_xl);
    cudaGetSymbolAddress((void**)&Wh,     g_Wh);
    cudaGetSymbolAddress((void**)&Wl,     g_Wl);

    static int smem_set = 0;
    if (!smem_set) {
        cudaFuncSetAttribute(gemm_mma2, cudaFuncAttributeMaxDynamicSharedMemorySize,
                             4 * 128 * PITCH * 4);
        smem_set = 1;
    }

    colemb_kernel<<<MCOLS, DD>>>(pW1, pb1, pW2, pb2, colemb);
    x0_kernel<<<NNODES, 256>>>(init, colemb, x0, x0h, x0l);

    // pre-convert all 9 weight matrices (transposed, split hi/lo)
    for (int b = 0; b < 3; b++)
        for (int l = 0; l < 3; l++) {
            int w = b * 3 + l;
            wconv_kernel<<<dim3(8, 8), dim3(32, 8)>>>(Wb[b] + (size_t)l * DD * DD,
                                                      Wh + (size_t)w * DD * DD,
                                                      Wl + (size_t)w * DD * DD);
        }

    const int NB = (NNODES + 255) / 256;
    const int EB = (NEDGE + 255) / 256;
    const int GSM = 4 * 128 * PITCH * 4;

    for (int b = 0; b < 3; b++) {
        branch_init<<<NB, 256>>>(deg, hist);
        edge_count<<<EB, 256>>>(ei[b], ea[b], deg, hist);
        dinv_kernel<<<NB, 256>>>(deg, dinv);
        scan_kernel<<<1, 1024>>>(hist, start, cur);
        scatter_kernel<<<EB, 256>>>(ei[b], ea[b], dinv, cur, src, nrm);

        for (int l = 0; l < 3; l++) {
            int w = b * 3 + l;
            const __nv_bfloat16* Ah = (l == 0) ? x0h : xh;
            const __nv_bfloat16* Al = (l == 0) ? x0l : xl;
            gemm_mma2<<<dim3(NPAD / 128, 2), 256, GSM>>>(Ah, Al,
                                                         Wh + (size_t)w * DD * DD,
                                                         Wl + (size_t)w * DD * DD, h);
            int last = (l == 2);
            agg_kernel<<<NNODES, 64>>>(h, src, nrm, start, dinv, bb[b] + l * DD,
                                       br[b], xh, xl, !last, last);
        }
    }

    attn_kernel<<<NNODES, 256>>>(br[0], br[1], br[2], watt, out);
}

// round 5
// speedup vs baseline: 1.4473x; 1.0498x over previous
#include <cuda_runtime.h>
#include <cuda_bf16.h>
#include <cstdint>

#define NNODES 20000
#define NPAD   20096            // 157 * 128
#define MCOLS  1024
#define NEDGE  640000
#define DD     256

// ---------------- scratch (__device__ globals; zero-initialized bss) ----------------
__device__ float g_colemb[MCOLS * DD];
__device__ float g_h[NPAD * DD];
__device__ float g_br0[NPAD * DD];
__device__ float g_br1[NPAD * DD];
__device__ float g_br2[NPAD * DD];
__device__ float g_deg[NNODES];
__device__ float g_dinv[NNODES];
__device__ int   g_hist[NNODES];
__device__ int   g_cur[NNODES];
__device__ int   g_start[NNODES + 1];
__device__ int   g_src[NEDGE];
__device__ float g_nrm[NEDGE];
// packed bf16 hi/lo planes (A operands), k-contiguous rows of 256
__device__ __nv_bfloat16 g_x0h[NPAD * DD];
__device__ __nv_bfloat16 g_x0l[NPAD * DD];
__device__ __nv_bfloat16 g_xh[NPAD * DD];
__device__ __nv_bfloat16 g_xl[NPAD * DD];
// transposed bf16 hi/lo weights: [9][n=256][k=256]
__device__ __nv_bfloat16 g_Wh[9 * DD * DD];
__device__ __nv_bfloat16 g_Wl[9 * DD * DD];

// ---------------- projection: col_emb ----------------
__global__ void colemb_kernel(const float* __restrict__ pW1, const float* __restrict__ pb1,
                              const float* __restrict__ pW2, const float* __restrict__ pb2,
                              float* __restrict__ colemb) {
    int j = blockIdx.x;
    int d = threadIdx.x;
    float jf = (float)j;
    float acc = pb2[d];
#pragma unroll
    for (int k = 0; k < 16; k++) {
        float hk = fmaxf(jf * pW1[k] + pb1[k], 0.f);
        acc += hk * pW2[k * DD + d];
    }
    colemb[j * DD + d] = acc;
}

// ---------------- x0: masked mean over nonzero cols -> bf16 hi/lo planes ----------------
__global__ void x0_kernel(const float* __restrict__ init, const float* __restrict__ colemb,
                          __nv_bfloat16* __restrict__ xh, __nv_bfloat16* __restrict__ xl) {
    int i = blockIdx.x;
    int t = threadIdx.x;  // 256
    __shared__ unsigned short nz[MCOLS];
    __shared__ int cnt;
    if (t == 0) cnt = 0;
    __syncthreads();
    const float* row = init + (size_t)i * MCOLS;
    for (int c = t; c < MCOLS; c += 256) {
        if (row[c] != 0.f) {
            int p = atomicAdd(&cnt, 1);
            nz[p] = (unsigned short)c;
        }
    }
    __syncthreads();
    int n = cnt;
    float acc = 0.f;
    for (int k = 0; k < n; k++) acc += colemb[(int)nz[k] * DD + t];
    float v = (n > 0) ? acc / (float)n : 0.f;
    size_t off = (size_t)i * DD + t;
    __nv_bfloat16 h = __float2bfloat16(v);
    xh[off] = h;
    xl[off] = __float2bfloat16(v - __bfloat162float(h));
}

// ---------------- weight convert: Wt_hi/lo[n][k] = bf16split(W[k][n]); grid.z = layer ----
__global__ void wconv_kernel(const float* __restrict__ W,
                             __nv_bfloat16* __restrict__ Ht, __nv_bfloat16* __restrict__ Lt) {
    __shared__ float tile[32][33];
    size_t base = (size_t)blockIdx.z * DD * DD;
    int n0 = blockIdx.x * 32, k0 = blockIdx.y * 32;
    int tx = threadIdx.x, ty = threadIdx.y;  // 32 x 8
#pragma unroll
    for (int i = 0; i < 32; i += 8)
        tile[ty + i][tx] = W[base + (size_t)(k0 + ty + i) * DD + n0 + tx];
    __syncthreads();
#pragma unroll
    for (int i = 0; i < 32; i += 8) {
        float v = tile[tx][ty + i];                 // W[k0+tx][n0+ty+i]
        __nv_bfloat16 h = __float2bfloat16(v);
        size_t o = base + (size_t)(n0 + ty + i) * DD + k0 + tx;
        Ht[o] = h;
        Lt[o] = __float2bfloat16(v - __bfloat162float(h));
    }
}

// ---------------- per-branch graph prep ----------------
__global__ void branch_init(float* __restrict__ deg, int* __restrict__ hist) {
    int i = blockIdx.x * blockDim.x + threadIdx.x;
    if (i < NNODES) { deg[i] = 1.0f; hist[i] = 0; }
}

__global__ void edge_count(const int* __restrict__ ei, const float* __restrict__ ea,
                           float* __restrict__ deg, int* __restrict__ hist) {
    int e = blockIdx.x * blockDim.x + threadIdx.x;
    if (e < NEDGE) {
        int c = ei[NEDGE + e];
        atomicAdd(&deg[c], ea[e]);
        atomicAdd(&hist[c], 1);
    }
}

__global__ void dinv_kernel(const float* __restrict__ deg, float* __restrict__ dinv) {
    int i = blockIdx.x * blockDim.x + threadIdx.x;
    if (i < NNODES) dinv[i] = rsqrtf(deg[i]);
}

__global__ void scan_kernel(const int* __restrict__ hist, int* __restrict__ start,
                            int* __restrict__ cur) {
    __shared__ int sm[1024];
    __shared__ int carry_s;
    int t = threadIdx.x;
    if (t == 0) carry_s = 0;
    __syncthreads();
    for (int c0 = 0; c0 < NNODES; c0 += 1024) {
        int idx = c0 + t;
        int v = (idx < NNODES) ? hist[idx] : 0;
        sm[t] = v;
        __syncthreads();
        for (int off = 1; off < 1024; off <<= 1) {
            int x = (t >= off) ? sm[t - off] : 0;
            __syncthreads();
            sm[t] += x;
            __syncthreads();
        }
        int incl = sm[t];
        int base = carry_s;
        __syncthreads();
        if (t == 1023) carry_s = base + incl;
        int excl = base + incl - v;
        if (idx < NNODES) { start[idx] = excl; cur[idx] = excl; }
        __syncthreads();
    }
    if (t == 0) start[NNODES] = carry_s;
}

__global__ void scatter_kernel(const int* __restrict__ ei, const float* __restrict__ ea,
                               const float* __restrict__ dinv, int* __restrict__ cur,
                               int* __restrict__ src, float* __restrict__ nrm) {
    int e = blockIdx.x * blockDim.x + threadIdx.x;
    if (e < NEDGE) {
        int r = ei[e];
        int c = ei[NEDGE + e];
        float n = dinv[r] * ea[e] * dinv[c];
        int p = atomicAdd(&cur[c], 1);
        src[p] = r;
        nrm[p] = n;
    }
}

// ================= split-bf16 HMMA GEMM (preconverted operands, ldmatrix) =================
// C[NPAD,256] = A @ W,  A bf16 hi/lo planes [row][k], W bf16 hi/lo [n][k].
// CTA tile 128(M)x128(N), K chunked by 64. 8 warps = 2(M) x 4(N), each warp 64x32
// via 4x4 m16n8k16 tiles. acc += Ah*Wh + Al*Wh + Ah*Wl.
#define KC 64
#define PITCH 36      // uint32 words per smem row (32 kpairs + 4 pad)

__device__ __forceinline__ void mma_bf16(float* c, const uint32_t* a, const uint32_t* b) {
    asm volatile(
        "mma.sync.aligned.m16n8k16.row.col.f32.bf16.bf16.f32 "
        "{%0,%1,%2,%3}, {%4,%5,%6,%7}, {%8,%9}, {%0,%1,%2,%3};"
        : "+f"(c[0]), "+f"(c[1]), "+f"(c[2]), "+f"(c[3])
        : "r"(a[0]), "r"(a[1]), "r"(a[2]), "r"(a[3]), "r"(b[0]), "r"(b[1]));
}
__device__ __forceinline__ void ldsm4(uint32_t* r, uint32_t addr) {
    asm volatile("ldmatrix.sync.aligned.m8n8.x4.shared.b16 {%0,%1,%2,%3}, [%4];"
        : "=r"(r[0]), "=r"(r[1]), "=r"(r[2]), "=r"(r[3]) : "r"(addr));
}
__device__ __forceinline__ void cp16(uint32_t smem_dst, const void* gsrc) {
    asm volatile("cp.async.cg.shared.global [%0], [%1], 16;" :: "r"(smem_dst), "l"(gsrc));
}

__global__ void __launch_bounds__(256, 2) gemm_mma2(
    const __nv_bfloat16* __restrict__ Ah_g, const __nv_bfloat16* __restrict__ Al_g,
    const __nv_bfloat16* __restrict__ Bh_g, const __nv_bfloat16* __restrict__ Bl_g,
    float* __restrict__ C) {
    extern __shared__ uint32_t smem[];
    uint32_t* sAh = smem;
    uint32_t* sAl = smem + 128 * PITCH;
    uint32_t* sBh = smem + 2 * 128 * PITCH;
    uint32_t* sBl = smem + 3 * 128 * PITCH;

    int tid = threadIdx.x;
    int lane = tid & 31, wid = tid >> 5;
    int g = lane >> 2, tig = lane & 3;
    int wm = wid & 1, wn = wid >> 1;
    int bm = blockIdx.x * 128;
    int bn = blockIdx.y * 128;

    uint32_t sAh_a = (uint32_t)__cvta_generic_to_shared(sAh);
    uint32_t sAl_a = (uint32_t)__cvta_generic_to_shared(sAl);
    uint32_t sBh_a = (uint32_t)__cvta_generic_to_shared(sBh);
    uint32_t sBl_a = (uint32_t)__cvta_generic_to_shared(sBl);

    // ldmatrix lane-address offsets (bytes):
    // A x4 tile (16m x 16k): lanes 0-15 -> rows r0+lane15 @k0-7; lanes 16-31 same rows @k8-15
    int lane15 = lane & 15;
    int khalf = lane >> 4;  // 0/1
    uint32_t A_loff = (uint32_t)((wm * 64 + lane15) * PITCH) * 4u + (uint32_t)khalf * 16u;
    // B x4 covers nt pair: lanes0-7 rows of nt @k0-7; 8-15 same @k8-15; 16-31 nt+1
    int bnrow = wn * 32 + (lane >> 4) * 8 + (lane & 7);
    uint32_t B_loff = (uint32_t)(bnrow * PITCH) * 4u + (uint32_t)((lane >> 3) & 1) * 16u;

    float acc[4][4][4];
#pragma unroll
    for (int mt = 0; mt < 4; mt++)
#pragma unroll
        for (int nt = 0; nt < 4; nt++)
#pragma unroll
            for (int q = 0; q < 4; q++) acc[mt][nt][q] = 0.f;

    for (int k0 = 0; k0 < DD; k0 += KC) {
        // ---- async loads: each array is 128 rows x 8 segs(16B); 4 segs/thread/array
#pragma unroll
        for (int i = 0; i < 4; i++) {
            int sl = tid + i * 256;
            int row = sl >> 3;
            int s = sl & 7;
            uint32_t so = (uint32_t)(row * PITCH + s * 4) * 4u;
            size_t ga = (size_t)(bm + row) * DD + k0 + s * 8;
            size_t gb = (size_t)(bn + row) * DD + k0 + s * 8;
            cp16(sAh_a + so, Ah_g + ga);
            cp16(sAl_a + so, Al_g + ga);
            cp16(sBh_a + so, Bh_g + gb);
            cp16(sBl_a + so, Bl_g + gb);
        }
        asm volatile("cp.async.commit_group;");
        asm volatile("cp.async.wait_group 0;");
        __syncthreads();

#pragma unroll
        for (int ks = 0; ks < 4; ks++) {
            uint32_t koff = (uint32_t)ks * 32u;
            uint32_t Bh[4][2], Bl[4][2];
#pragma unroll
            for (int ntp = 0; ntp < 2; ntp++) {
                uint32_t r[4];
                uint32_t off = B_loff + (uint32_t)(ntp * 16 * PITCH) * 4u + koff;
                ldsm4(r, sBh_a + off);
                Bh[2 * ntp][0] = r[0]; Bh[2 * ntp][1] = r[1];
                Bh[2 * ntp + 1][0] = r[2]; Bh[2 * ntp + 1][1] = r[3];
                ldsm4(r, sBl_a + off);
                Bl[2 * ntp][0] = r[0]; Bl[2 * ntp][1] = r[1];
                Bl[2 * ntp + 1][0] = r[2]; Bl[2 * ntp + 1][1] = r[3];
            }
#pragma unroll
            for (int mt = 0; mt < 4; mt++) {
                uint32_t off = A_loff + (uint32_t)(mt * 16 * PITCH) * 4u + koff;
                uint32_t Ah[4], Al[4];
                ldsm4(Ah, sAh_a + off);
                ldsm4(Al, sAl_a + off);
#pragma unroll
                for (int nt = 0; nt < 4; nt++) {
                    mma_bf16(acc[mt][nt], Ah, Bh[nt]);
                    mma_bf16(acc[mt][nt], Al, Bh[nt]);
                    mma_bf16(acc[mt][nt], Ah, Bl[nt]);
                }
            }
        }
        __syncthreads();
    }

    // ---- epilogue
#pragma unroll
    for (int mt = 0; mt < 4; mt++) {
        int row = bm + wm * 64 + mt * 16 + g;
#pragma unroll
        for (int nt = 0; nt < 4; nt++) {
            int col = bn + wn * 32 + nt * 8 + tig * 2;
            *(float2*)&C[(size_t)row * DD + col] = make_float2(acc[mt][nt][0], acc[mt][nt][1]);
            *(float2*)&C[(size_t)(row + 8) * DD + col] = make_float2(acc[mt][nt][2], acc[mt][nt][3]);
        }
    }
}

// ---------------- aggregation (+ optional relu'd bf16 hi/lo pack for next layer) --------
__global__ void __launch_bounds__(64) agg_kernel(const float* __restrict__ h, const int* __restrict__ src,
                           const float* __restrict__ nrm, const int* __restrict__ start,
                           const float* __restrict__ dinv, const float* __restrict__ bias,
                           float* __restrict__ out,
                           __nv_bfloat16* __restrict__ xh, __nv_bfloat16* __restrict__ xl,
                           int pack, int wf32) {
    int i = blockIdx.x;
    int t = threadIdx.x;  // 64, float4 each
    int s = start[i];
    int e = start[i + 1];
    float4 a0 = make_float4(0.f, 0.f, 0.f, 0.f);
    float4 a1 = make_float4(0.f, 0.f, 0.f, 0.f);
    float4 a2 = make_float4(0.f, 0.f, 0.f, 0.f);
    float4 a3 = make_float4(0.f, 0.f, 0.f, 0.f);
    int k = s;
    for (; k + 7 < e; k += 8) {
        int r0 = src[k], r1 = src[k + 1], r2 = src[k + 2], r3 = src[k + 3];
        int r4 = src[k + 4], r5 = src[k + 5], r6 = src[k + 6], r7 = src[k + 7];
        float w0 = nrm[k], w1 = nrm[k + 1], w2 = nrm[k + 2], w3 = nrm[k + 3];
        float w4 = nrm[k + 4], w5 = nrm[k + 5], w6 = nrm[k + 6], w7 = nrm[k + 7];
        float4 v0 = *(const float4*)&h[(size_t)r0 * DD + t * 4];
        float4 v1 = *(const float4*)&h[(size_t)r1 * DD + t * 4];
        float4 v2 = *(const float4*)&h[(size_t)r2 * DD + t * 4];
        float4 v3 = *(const float4*)&h[(size_t)r3 * DD + t * 4];
        float4 v4 = *(const float4*)&h[(size_t)r4 * DD + t * 4];
        float4 v5 = *(const float4*)&h[(size_t)r5 * DD + t * 4];
        float4 v6 = *(const float4*)&h[(size_t)r6 * DD + t * 4];
        float4 v7 = *(const float4*)&h[(size_t)r7 * DD + t * 4];
        a0.x += w0 * v0.x; a0.y += w0 * v0.y; a0.z += w0 * v0.z; a0.w += w0 * v0.w;
        a1.x += w1 * v1.x; a1.y += w1 * v1.y; a1.z += w1 * v1.z; a1.w += w1 * v1.w;
        a2.x += w2 * v2.x; a2.y += w2 * v2.y; a2.z += w2 * v2.z; a2.w += w2 * v2.w;
        a3.x += w3 * v3.x; a3.y += w3 * v3.y; a3.z += w3 * v3.z; a3.w += w3 * v3.w;
        a0.x += w4 * v4.x; a0.y += w4 * v4.y; a0.z += w4 * v4.z; a0.w += w4 * v4.w;
        a1.x += w5 * v5.x; a1.y += w5 * v5.y; a1.z += w5 * v5.z; a1.w += w5 * v5.w;
        a2.x += w6 * v6.x; a2.y += w6 * v6.y; a2.z += w6 * v6.z; a2.w += w6 * v6.w;
        a3.x += w7 * v7.x; a3.y += w7 * v7.y; a3.z += w7 * v7.z; a3.w += w7 * v7.w;
    }
    for (; k < e; k++) {
        int r = src[k];
        float w = nrm[k];
        float4 v = *(const float4*)&h[(size_t)r * DD + t * 4];
        a0.x += w * v.x; a0.y += w * v.y; a0.z += w * v.z; a0.w += w * v.w;
    }
    float di = dinv[i];
    float sn = di * di;
    float4 hv = *(const float4*)&h[(size_t)i * DD + t * 4];
    float4 bv = *(const float4*)&bias[t * 4];
    float4 acc;
    acc.x = a0.x + a1.x + a2.x + a3.x + sn * hv.x + bv.x;
    acc.y = a0.y + a1.y + a2.y + a3.y + sn * hv.y + bv.y;
    acc.z = a0.z + a1.z + a2.z + a3.z + sn * hv.z + bv.z;
    acc.w = a0.w + a1.w + a2.w + a3.w + sn * hv.w + bv.w;
    if (wf32) *(float4*)&out[(size_t)i * DD + t * 4] = acc;
    if (pack) {
        float r0 = fmaxf(acc.x, 0.f), r1 = fmaxf(acc.y, 0.f);
        float r2 = fmaxf(acc.z, 0.f), r3 = fmaxf(acc.w, 0.f);
        __nv_bfloat162 h01, h23, l01, l23;
        h01.x = __float2bfloat16(r0); h01.y = __float2bfloat16(r1);
        h23.x = __float2bfloat16(r2); h23.y = __float2bfloat16(r3);
        l01.x = __float2bfloat16(r0 - __bfloat162float(h01.x));
        l01.y = __float2bfloat16(r1 - __bfloat162float(h01.y));
        l23.x = __float2bfloat16(r2 - __bfloat162float(h23.x));
        l23.y = __float2bfloat16(r3 - __bfloat162float(h23.y));
        uint2 hp, lp;
        hp.x = *reinterpret_cast<uint32_t*>(&h01);
        hp.y = *reinterpret_cast<uint32_t*>(&h23);
        lp.x = *reinterpret_cast<uint32_t*>(&l01);
        lp.y = *reinterpret_cast<uint32_t*>(&l23);
        reinterpret_cast<uint2*>(xh)[(size_t)i * 64 + t] = hp;
        reinterpret_cast<uint2*>(xl)[(size_t)i * 64 + t] = lp;
    }
}

// ---------------- meta-path attention ----------------
__global__ void attn_kernel(const float* __restrict__ b0, const float* __restrict__ b1,
                            const float* __restrict__ b2, const float* __restrict__ watt,
                            float* __restrict__ out) {
    int i = blockIdx.x;
    int t = threadIdx.x;  // 256
    size_t off = (size_t)i * DD + t;
    float x0v = fmaxf(b0[off], 0.f);
    float x1v = fmaxf(b1[off], 0.f);
    float x2v = fmaxf(b2[off], 0.f);
    float w = watt[t];
    float s0 = x0v * w, s1 = x1v * w, s2 = x2v * w;
#pragma unroll
    for (int o = 16; o; o >>= 1) {
        s0 += __shfl_xor_sync(0xffffffffu, s0, o);
        s1 += __shfl_xor_sync(0xffffffffu, s1, o);
        s2 += __shfl_xor_sync(0xffffffffu, s2, o);
    }
    __shared__ float sm[3][8];
    __shared__ float sw[3];
    int wid = t >> 5, ln = t & 31;
    if (ln == 0) { sm[0][wid] = s0; sm[1][wid] = s1; sm[2][wid] = s2; }
    __syncthreads();
    if (t == 0) {
        float t0 = 0.f, t1 = 0.f, t2 = 0.f;
#pragma unroll
        for (int kk = 0; kk < 8; kk++) { t0 += sm[0][kk]; t1 += sm[1][kk]; t2 += sm[2][kk]; }
        float mx = fmaxf(t0, fmaxf(t1, t2));
        float e0 = expf(t0 - mx), e1 = expf(t1 - mx), e2 = expf(t2 - mx);
        float inv = 1.f / (e0 + e1 + e2);
        sw[0] = e0 * inv; sw[1] = e1 * inv; sw[2] = e2 * inv;
    }
    __syncthreads();
    out[off] = sw[0] * x0v + sw[1] * x1v + sw[2] * x2v;
}

// ---------------- launcher ----------------
extern "C" void kernel_launch(void* const* d_in, const int* in_sizes, int n_in,
                              void* d_out, int out_size) {
    const float* init = (const float*)d_in[0];
    const int*   ei[3] = {(const int*)d_in[1], (const int*)d_in[2], (const int*)d_in[3]};
    const float* ea[3] = {(const float*)d_in[4], (const float*)d_in[5], (const float*)d_in[6]};
    const float* pW1 = (const float*)d_in[7];
    const float* pb1 = (const float*)d_in[8];
    const float* pW2 = (const float*)d_in[9];
    const float* pb2 = (const float*)d_in[10];
    const float* Wb[3] = {(const float*)d_in[11], (const float*)d_in[13], (const float*)d_in[15]};
    const float* bb[3] = {(const float*)d_in[12], (const float*)d_in[14], (const float*)d_in[16]};
    const float* watt = (const float*)d_in[17];
    float* out = (float*)d_out;

    float *colemb, *h, *deg, *dinv, *nrm;
    float *br[3];
    int *hist, *cur, *start, *src;
    __nv_bfloat16 *x0h, *x0l, *xh, *xl, *Wh, *Wl;
    cudaGetSymbolAddress((void**)&colemb, g_colemb);
    cudaGetSymbolAddress((void**)&h,      g_h);
    cudaGetSymbolAddress((void**)&br[0],  g_br0);
    cudaGetSymbolAddress((void**)&br[1],  g_br1);
    cudaGetSymbolAddress((void**)&br[2],  g_br2);
    cudaGetSymbolAddress((void**)&deg,    g_deg);
    cudaGetSymbolAddress((void**)&dinv,   g_dinv);
    cudaGetSymbolAddress((void**)&hist,   g_hist);
    cudaGetSymbolAddress((void**)&cur,    g_cur);
    cudaGetSymbolAddress((void**)&start,  g_start);
    cudaGetSymbolAddress((void**)&src,    g_src);
    cudaGetSymbolAddress((void**)&nrm,    g_nrm);
    cudaGetSymbolAddress((void**)&x0h,    g_x0h);
    cudaGetSymbolAddress((void**)&x0l,    g_x0l);
    cudaGetSymbolAddress((void**)&xh,     g_xh);
    cudaGetSymbolAddress((void**)&xl,     g_xl);
    cudaGetSymbolAddress((void**)&Wh,     g_Wh);
    cudaGetSymbolAddress((void**)&Wl,     g_Wl);

    static int smem_set = 0;
    if (!smem_set) {
        cudaFuncSetAttribute(gemm_mma2, cudaFuncAttributeMaxDynamicSharedMemorySize,
                             4 * 128 * PITCH * 4);
        smem_set = 1;
    }

    const int NB = (NNODES + 255) / 256;
    const int EB = (NEDGE + 255) / 256;
    const int GSM = 4 * 128 * PITCH * 4;

    // launches 1-5
    colemb_kernel<<<MCOLS, DD>>>(pW1, pb1, pW2, pb2, colemb);
    x0_kernel<<<NNODES, 256>>>(init, colemb, x0h, x0l);
    for (int b = 0; b < 3; b++)
        wconv_kernel<<<dim3(8, 8, 3), dim3(32, 8)>>>(Wb[b],
                                                     Wh + (size_t)(b * 3) * DD * DD,
                                                     Wl + (size_t)(b * 3) * DD * DD);

    for (int b = 0; b < 3; b++) {
        // launch #6 overall = gemm(b0,l0): profiled by ncu (-s 5 -c 1)
        gemm_mma2<<<dim3(NPAD / 128, 2), 256, GSM>>>(b == 0 ? x0h : x0h, b == 0 ? x0l : x0l,
                                                     Wh + (size_t)(b * 3) * DD * DD,
                                                     Wl + (size_t)(b * 3) * DD * DD, h);
        branch_init<<<NB, 256>>>(deg, hist);
        edge_count<<<EB, 256>>>(ei[b], ea[b], deg, hist);
        dinv_kernel<<<NB, 256>>>(deg, dinv);
        scan_kernel<<<1, 1024>>>(hist, start, cur);
        scatter_kernel<<<EB, 256>>>(ei[b], ea[b], dinv, cur, src, nrm);
        agg_kernel<<<NNODES, 64>>>(h, src, nrm, start, dinv, bb[b] + 0 * DD,
                                   br[b], xh, xl, 1, 0);

        for (int l = 1; l < 3; l++) {
            int w = b * 3 + l;
            gemm_mma2<<<dim3(NPAD / 128, 2), 256, GSM>>>(xh, xl,
                                                         Wh + (size_t)w * DD * DD,
                                                         Wl + (size_t)w * DD * DD, h);
            int last = (l == 2);
            agg_kernel<<<NNODES, 64>>>(h, src, nrm, start, dinv, bb[b] + l * DD,
                                       br[b], xh, xl, !last, last);
        }
    }

    attn_kernel<<<NNODES, 256>>>(br[0], br[1], br[2], watt, out);
}